// round 1
// baseline (speedup 1.0000x reference)
#include <cuda_runtime.h>
#include <math.h>

// ---------------------------------------------------------------------------
// Tree-reduce with fused conv gate.
//   Per level: lrg[o,l] = sum_{c,k} in[c,2l+k] * W[o,c,k] + b[o]
//   out = l * sig(g) + tanh(r) * (1 - sig(g)),  channels split 512/512/512.
//
// Data layout trick: activations stored position-major [b][pos][512ch], so the
// K=1024 input vector of an output position is contiguous (two adjacent
// 512-vectors). W is pre-permuted once to Wp[o][kk*512 + c] to match.
//
// Scratch: one slab of 8192 positions per batch. Level k output lives at
// offset off_k = 8192 - (8192 >> k). Level 0 ("cur") at 0; the staging
// transpose of h's prefix lives at off_1 (overwritten later by level 1).
// ---------------------------------------------------------------------------

#define BATCH 16
#define CCH   512
#define LMAX  4096
#define KDIM  1024
#define SLAB  8192
#define BM    64      // output positions per block
#define BK    32      // K-tile
#define NROWS 96      // 32 base channels x 3 gate groups
#define XROW  68      // padded smem row for x tile

__device__ float g_buf[(size_t)BATCH * SLAB * CCH];   // 268 MB scratch
__device__ float g_wp[1536 * KDIM];                   // permuted W

// ---------------------------------------------------------------------------
__global__ void permute_w(const float* __restrict__ W) {
    int i = blockIdx.x * blockDim.x + threadIdx.x;
    if (i >= 1536 * KDIM) return;
    int o  = i >> 10;
    int kp = i & 1023;          // kp = kk*512 + c
    int kk = kp >> 9;
    int c  = kp & 511;
    g_wp[i] = W[o * KDIM + c * 2 + kk];
}

// ---------------------------------------------------------------------------
// Transpose h[b][c][j] into position-major layout, splitting destinations:
//   j <  M        -> staging (off_1 region)   [feeds the level-0 partial conv]
//   M <= j < N    -> cur region, position j - M/2   [the raw suffix]
// ---------------------------------------------------------------------------
__global__ void transpose_init(const float* __restrict__ h,
                               const int* __restrict__ Np) {
    __shared__ float tile[32][33];
    int b = blockIdx.z;
    int N = Np[b];
    int s = 31 - __clz(N);
    int Nfp2 = 1 << s;
    int M2 = N - Nfp2;          // M/2
    int M  = 2 * M2;
    int j0 = blockIdx.x * 32;
    int c0 = blockIdx.y * 32;
    if (j0 >= N) return;

    int tx = threadIdx.x & 31, ty = threadIdx.x >> 5;
    const float* hb = h + (size_t)b * CCH * LMAX;
    #pragma unroll
    for (int i = 0; i < 4; i++) {
        int c = c0 + ty + i * 8;
        tile[ty + i * 8][tx] = hb[(size_t)c * LMAX + j0 + tx];
    }
    __syncthreads();
    float* bufb = g_buf + (size_t)b * SLAB * CCH;
    #pragma unroll
    for (int i = 0; i < 4; i++) {
        int j = j0 + ty + i * 8;
        float v = tile[tx][ty + i * 8];
        int c = c0 + tx;
        if (j < M) {
            bufb[(size_t)(4096 + j) * CCH + c] = v;        // staging @ off_1
        } else if (j < N) {
            bufb[(size_t)(j - M2) * CCH + c] = v;          // cur @ off_0
        }
    }
}

// ---------------------------------------------------------------------------
// One conv-reduce level. level==0 is the partial fold (P = N - Nfp2, input =
// staging); level>=1 is a tree level (P = (Nfp2 >> (level-1)) / 2).
// Block tile: 64 positions x 32 base channels (x3 gate rows). 256 threads,
// each computes a 4-position x 2-channel x 3-gate micro-tile (24 acc).
// ---------------------------------------------------------------------------
__global__ __launch_bounds__(256)
void conv_level(const int* __restrict__ Np, const float* __restrict__ bias,
                int level, int off_in, int off_out, int maxP) {
    int b = blockIdx.z;
    int N = Np[b];
    int s = 31 - __clz(N);
    int Nfp2 = 1 << s;
    int P;
    if (level == 0) {
        P = N - Nfp2;
    } else {
        int len_in = Nfp2 >> (level - 1);
        P = (len_in >= 2) ? (len_in >> 1) : 0;
    }
    int p0 = blockIdx.x * BM;
    if (p0 >= P) return;

    const float* __restrict__ in  = g_buf + ((size_t)b * SLAB + off_in)  * CCH;
    float*       __restrict__ out = g_buf + ((size_t)b * SLAB + off_out) * CCH;
    int cblk = blockIdx.y;   // 0..15

    __shared__ float xs[BK][XROW];    // x tile  [k][pos]
    __shared__ float ws[BK][NROWS];   // W tile  [k][g*32 + c]

    int tid = threadIdx.x;
    int tp = tid >> 4;   // 0..15 -> positions tp*4 .. tp*4+3
    int tc = tid & 15;   // channels tc*2, tc*2+1

    float acc[4][6];
    #pragma unroll
    for (int p = 0; p < 4; p++)
        #pragma unroll
        for (int q = 0; q < 6; q++) acc[p][q] = 0.0f;

    // --- global load plans (register-staged prefetch) ---
    const float4* xg[2]; int xpos[2], xkq[2];
    #pragma unroll
    for (int a = 0; a < 2; a++) {
        int idx = tid + a * 256;
        int pos = idx >> 3, kq = idx & 7;
        int lc = min(p0 + pos, maxP - 1);
        xg[a]  = (const float4*)(in + (size_t)(2 * lc) * CCH) + kq;
        xpos[a] = pos; xkq[a] = kq;
    }
    const float4* wg[3]; int wrow[3], wkq[3];
    #pragma unroll
    for (int a = 0; a < 3; a++) {
        int idx = tid + a * 256;
        int row = idx >> 3, kq = idx & 7;
        int grow = (row >> 5) * 512 + cblk * 32 + (row & 31);
        wg[a]  = (const float4*)(g_wp + (size_t)grow * KDIM) + kq;
        wrow[a] = row; wkq[a] = kq;
    }

    float4 xr[2], wr[3];
    #pragma unroll
    for (int a = 0; a < 2; a++) xr[a] = xg[a][0];
    #pragma unroll
    for (int a = 0; a < 3; a++) wr[a] = wg[a][0];

    const int NT = KDIM / BK;   // 32
    for (int t = 0; t < NT; t++) {
        #pragma unroll
        for (int a = 0; a < 2; a++) {
            int k4 = xkq[a] * 4;
            xs[k4 + 0][xpos[a]] = xr[a].x;
            xs[k4 + 1][xpos[a]] = xr[a].y;
            xs[k4 + 2][xpos[a]] = xr[a].z;
            xs[k4 + 3][xpos[a]] = xr[a].w;
        }
        #pragma unroll
        for (int a = 0; a < 3; a++) {
            int k4 = wkq[a] * 4;
            ws[k4 + 0][wrow[a]] = wr[a].x;
            ws[k4 + 1][wrow[a]] = wr[a].y;
            ws[k4 + 2][wrow[a]] = wr[a].z;
            ws[k4 + 3][wrow[a]] = wr[a].w;
        }
        __syncthreads();
        if (t + 1 < NT) {
            #pragma unroll
            for (int a = 0; a < 2; a++) xr[a] = xg[a][(t + 1) * 8];
            #pragma unroll
            for (int a = 0; a < 3; a++) wr[a] = wg[a][(t + 1) * 8];
        }
        #pragma unroll 8
        for (int k = 0; k < BK; k++) {
            float4 av = *(const float4*)&xs[k][tp * 4];
            float2 w0 = *(const float2*)&ws[k][0  + tc * 2];
            float2 w1 = *(const float2*)&ws[k][32 + tc * 2];
            float2 w2 = *(const float2*)&ws[k][64 + tc * 2];
            float ap[4] = {av.x, av.y, av.z, av.w};
            float wl[6] = {w0.x, w0.y, w1.x, w1.y, w2.x, w2.y};
            #pragma unroll
            for (int p = 0; p < 4; p++)
                #pragma unroll
                for (int q = 0; q < 6; q++)
                    acc[p][q] += ap[p] * wl[q];
        }
        __syncthreads();
    }

    // --- fused gate epilogue ---
    int chb = cblk * 32 + tc * 2;
    float bl0 = bias[chb],          bl1 = bias[chb + 1];
    float br0 = bias[512 + chb],    br1 = bias[512 + chb + 1];
    float bg0 = bias[1024 + chb],   bg1 = bias[1024 + chb + 1];
    #pragma unroll
    for (int p = 0; p < 4; p++) {
        int l = p0 + tp * 4 + p;
        if (l >= P) continue;
        float lv0 = acc[p][0] + bl0;
        float lv1 = acc[p][1] + bl1;
        float rv0 = tanhf(acc[p][2] + br0);
        float rv1 = tanhf(acc[p][3] + br1);
        float gv0 = 1.0f / (1.0f + expf(-(acc[p][4] + bg0)));
        float gv1 = 1.0f / (1.0f + expf(-(acc[p][5] + bg1)));
        float2 ov;
        ov.x = lv0 * gv0 + rv0 * (1.0f - gv0);
        ov.y = lv1 * gv1 + rv1 * (1.0f - gv1);
        *(float2*)&out[(size_t)l * CCH + chb] = ov;
    }
}

// ---------------------------------------------------------------------------
__global__ void extract(float* __restrict__ out, const int* __restrict__ Np) {
    int b = blockIdx.x;
    int N = Np[b];
    int s = 31 - __clz(N);
    int off = SLAB - (SLAB >> s);
    int c = threadIdx.x;
    out[b * CCH + c] = g_buf[((size_t)b * SLAB + off) * CCH + c];
}

// ---------------------------------------------------------------------------
extern "C" void kernel_launch(void* const* d_in, const int* in_sizes, int n_in,
                              void* d_out, int out_size) {
    const float* h    = (const float*)d_in[0];
    const float* W    = (const float*)d_in[1];
    const float* bias = (const float*)d_in[2];
    const int*   N    = (const int*)d_in[3];
    float* out = (float*)d_out;

    permute_w<<<(1536 * KDIM + 255) / 256, 256>>>(W);

    dim3 tg(LMAX / 32, CCH / 32, BATCH);
    transpose_init<<<tg, 256>>>(h, N);

    // level 0: partial fold of the first M elements (P_b = N - Nfp2 <= 2047)
    {
        int maxP = 2048;
        dim3 g((maxP + BM - 1) / BM, 16, BATCH);
        conv_level<<<g, 256>>>(N, bias, 0, 4096, 0, maxP);
    }

    // tree levels
    int off_in = 0;
    for (int k = 1; k <= 12; k++) {
        int off_out = SLAB - (SLAB >> k);
        int maxP = LMAX >> k;
        dim3 g((maxP + BM - 1) / BM, 16, BATCH);
        conv_level<<<g, 256>>>(N, bias, k, off_in, off_out, maxP);
        off_in = off_out;
    }

    extract<<<BATCH, CCH>>>(out, N);
}